// round 11
// baseline (speedup 1.0000x reference)
#include <cuda_runtime.h>
#include <cstdint>

// Fixed shapes from setup_inputs
#define BS      32
#define TT      50
#define HH      104
#define WW      104
#define HWP     (HH*WW)          // 10816
#define AA      3
#define CH      75               // 3 * 25
#define NC      20               // NUM_CLASSES - 1
#define NCELLS  (BS*AA*HWP)      // 1,038,336
#define NVEC    (NCELLS/4)       // 259,584
#define VEC_PER_PLANE (HWP/4)    // 2704

#define THREADS  256
#define NW       (THREADS/32)
#define DBLOCKS  254             // dense blocks: 254*256*4 = 260,096 >= NVEC (guarded)
#define DSTRIDE  (DBLOCKS*THREADS)
#define SBLOCKS  200             // sparse blocks: 200*8 warps = 1600 targets
#define BLOCKS   (DBLOCKS + SBLOCKS)

// Persistent scratch (zero-init at load; finalizing block resets to zero so
// every graph replay starts clean). Banked to avoid single-address RED pileup.
__device__ double g_accB[6][8];   // banked: sx, sy, sw, sh, sobj1, scls
__device__ double g_obj2B[32];    // banked dense/noobj accumulator
__device__ int    g_npos;
__device__ int    g_done;

__constant__ float c_saw[3] = {14.5f, 19.5f, 46.625f};   // ANCHORS / 8
__constant__ float c_sah[3] = {11.25f, 24.75f, 40.75f};

// softplus with the reference's clip semantics: for z beyond ~16.6, fp32
// sigmoid rounds to 1 -> ref's log(1-p) clips at -100 -> value 100.
__device__ __forceinline__ float spc(float z) {
    float s = __logf(1.0f + __expf(z));
    return (z > 16.6f) ? 100.0f : s;
}

struct TgtL {
    bool  valid;
    int   gi, gj, bn, cls;
    float gx, gy, gw, gh;
    float iou0, iou1, iou2;
};

__device__ __forceinline__ void light_target(const float* __restrict__ tg,
                                             int b, int t, TgtL& o) {
    const float* p = tg + ((size_t)b * TT + t) * 5;
    float cx = p[0], cy = p[1], w = p[2], h = p[3], cl = p[4];
    o.valid = (cx + cy + w + h + cl) > 0.0f;
    o.gx = cx * (float)WW;  o.gy = cy * (float)HH;
    o.gw = w  * (float)WW;  o.gh = h  * (float)HH;
    o.gi = (int)o.gx;       o.gj = (int)o.gy;
    float ious[3];
    float best = -1.0f; int bn = 0;
    #pragma unroll
    for (int a = 0; a < 3; a++) {
        float aw = c_saw[a], ah = c_sah[a];
        float inter = fmaxf(fminf(o.gw, aw) + 1.0f, 0.0f) *
                      fmaxf(fminf(o.gh, ah) + 1.0f, 0.0f);
        float area_g = (o.gw + 1.0f) * (o.gh + 1.0f);
        float area_a = (aw + 1.0f) * (ah + 1.0f);
        float iou = inter / (area_g + area_a - inter + 1e-16f);  // precise div
        ious[a] = iou;
        if (iou > best) { best = iou; bn = a; }
    }
    o.iou0 = ious[0]; o.iou1 = ious[1]; o.iou2 = ious[2];
    o.bn = bn;
    o.cls = (int)cl;
}

__device__ __forceinline__ float get_iou(const TgtL& o, int a) {
    return a == 0 ? o.iou0 : (a == 1 ? o.iou1 : o.iou2);
}

__global__ void __launch_bounds__(THREADS)
k_fused(const float* __restrict__ inp,
        const float* __restrict__ tg,
        float* __restrict__ out) {
    // staging: per-warp slots, no smem atomics
    __shared__ double s_w[NW][7];    // [warp][0..5 losses, 6 nsub]
    __shared__ int    s_np[NW];
    __shared__ float  ws[NW];

    const int tid  = threadIdx.x;
    const int lane = tid & 31;
    const int wid  = tid >> 5;
    const bool dense_block = (blockIdx.x < DBLOCKS);

    if (dense_block) {
        // ============== dense conf softplus, 4 float4 per thread ==========
        const int i0 = blockIdx.x * THREADS + tid;
        float4 z[4];
        bool ok[4];
        #pragma unroll
        for (int r = 0; r < 4; r++) {
            int v = i0 + r * DSTRIDE;
            ok[r] = (v < NVEC);
            if (ok[r]) {
                int plane = v / VEC_PER_PLANE;      // const-div -> mulhi
                int off   = (v - plane * VEC_PER_PLANE) * 4;
                int b = plane / AA, a = plane - b * AA;
                z[r] = *(const float4*)(inp +
                    ((size_t)(b * CH + a * 25 + 4)) * HWP + off);
            }
        }
        float dsum = 0.0f;
        #pragma unroll
        for (int r = 0; r < 4; r++) {
            if (ok[r])
                dsum += spc(z[r].x) + spc(z[r].y) + spc(z[r].z) + spc(z[r].w);
        }
        #pragma unroll
        for (int o = 16; o > 0; o >>= 1)
            dsum += __shfl_down_sync(0xFFFFFFFFu, dsum, o);
        if (lane == 0) ws[wid] = dsum;
        __syncthreads();
        if (tid == 0) {
            float dtot = 0.0f;
            #pragma unroll
            for (int k = 0; k < NW; k++) dtot += ws[k];
            atomicAdd(&g_obj2B[blockIdx.x & 31], (double)dtot);
        }
    } else {
        // ============== sparse: warp-per-target (1600 warps) ==============
        // zero this warp's staging (own-warp writes; no cross-warp race yet)
        if (lane < 7) s_w[wid][lane] = 0.0;
        if (lane == 0) s_np[wid] = 0;

        const int swarp = (blockIdx.x - DBLOCKS) * NW + wid;
        const int b = swarp / TT, t = swarp % TT;
        TgtL me;
        light_target(tg, b, t, me);
        bool live = me.valid && me.gi >= 0 && me.gi < WW &&
                    me.gj >= 0 && me.gj < HH;          // warp-uniform
        if (live) {
            // ---- PREFETCH: issue gather + noobj loads before the scan ----
            const float* base = inp + ((size_t)(b * CH + me.bn * 25)) * HWP
                                    + me.gj * WW + me.gi;
            float z_main = 0.0f, z_no = 0.0f;
            if (lane < 25)
                z_main = base[(size_t)lane * HWP];
            if (lane >= 25 && lane < 28) {
                int a = lane - 25;
                z_no = inp[((size_t)(b * CH + a * 25 + 4)) * HWP
                           + me.gj * WW + me.gi];
            }

            // ---- peer scan (overlaps with in-flight loads) ----
            bool conflict = false;
            unsigned bits = 0u;
            bool dup0 = false, dup1 = false, dup2 = false;
            #pragma unroll
            for (int r = 0; r < 2; r++) {
                int t2 = lane + r * 32;
                TgtL o; o.valid = false;
                if (t2 < TT) light_target(tg, b, t2, o);
                bool inb = o.valid && o.gi >= 0 && o.gi < WW &&
                           o.gj >= 0 && o.gj < HH;
                bool mc  = inb && (o.gi == me.gi) && (o.gj == me.gj);
                bool mbn = mc && (o.bn == me.bn);
                if (__ballot_sync(0xFFFFFFFFu, mbn && (t2 > t))) conflict = true;
                unsigned bv = mbn ? (1u << o.cls) : 0u;
                #pragma unroll
                for (int s = 16; s > 0; s >>= 1)
                    bv |= __shfl_xor_sync(0xFFFFFFFFu, bv, s);
                bits |= bv;
                if (__ballot_sync(0xFFFFFFFFu, mc && (o.iou0 > 0.5f) && (t2 < t))) dup0 = true;
                if (__ballot_sync(0xFFFFFFFFu, mc && (o.iou1 > 0.5f) && (t2 < t))) dup1 = true;
                if (__ballot_sync(0xFFFFFFFFu, mc && (o.iou2 > 0.5f) && (t2 < t))) dup2 = true;
            }

            // ---- per-lane losses (logit-space BCE: t*spc(-z)+(1-t)*spc(z)) ----
            float v = 0.0f;
            if (!conflict && lane < 25) {
                float z = z_main;
                if (lane == 0) {
                    float tx = me.gx - (float)me.gi;
                    v = tx * spc(-z) + (1.0f - tx) * spc(z);
                } else if (lane == 1) {
                    float ty = me.gy - (float)me.gj;
                    v = ty * spc(-z) + (1.0f - ty) * spc(z);
                } else if (lane == 2) {
                    float tw = logf(me.gw / c_saw[me.bn] + 1e-16f);
                    float d = z - tw; v = d * d;
                } else if (lane == 3) {
                    float th = logf(me.gh / c_sah[me.bn] + 1e-16f);
                    float d = z - th; v = d * d;
                } else if (lane == 4) {
                    v = spc(-z);                      // -max(log(sigmoid), -100)
                } else {
                    bool tpos = (bits >> (lane - 5)) & 1u;
                    v = tpos ? spc(-z) : spc(z);
                }
            }

            // noobj subtraction: lanes 25..27 handle anchors 0..2
            float nsub = 0.0f;
            if (lane >= 25 && lane < 28) {
                int a = lane - 25;
                bool dup = (a == 0) ? dup0 : (a == 1 ? dup1 : dup2);
                if (get_iou(me, a) > 0.5f && !dup) nsub = spc(z_no);
            }

            float clsv = (lane >= 5 && lane < 25) ? v : 0.0f;
            #pragma unroll
            for (int s = 16; s > 0; s >>= 1) {
                clsv += __shfl_xor_sync(0xFFFFFFFFu, clsv, s);
                nsub += __shfl_xor_sync(0xFFFFFFFFu, nsub, s);
            }
            float v1 = __shfl_sync(0xFFFFFFFFu, v, 1);
            float v2 = __shfl_sync(0xFFFFFFFFu, v, 2);
            float v3 = __shfl_sync(0xFFFFFFFFu, v, 3);
            float v4 = __shfl_sync(0xFFFFFFFFu, v, 4);

            if (lane == 0) {
                s_w[wid][6] = (double)nsub;
                if (!conflict) {
                    s_w[wid][0] = (double)v;
                    s_w[wid][1] = (double)v1;
                    s_w[wid][2] = (double)v2;
                    s_w[wid][3] = (double)v3;
                    s_w[wid][4] = (double)v4;
                    s_w[wid][5] = (double)clsv;
                    s_np[wid] = 1;
                }
            }
        }
        __syncthreads();
        if (tid == 0) {
            double acc[7] = {0, 0, 0, 0, 0, 0, 0};
            int np = 0;
            #pragma unroll
            for (int w = 0; w < NW; w++) {
                #pragma unroll
                for (int k = 0; k < 7; k++) acc[k] += s_w[w][k];
                np += s_np[w];
            }
            const int bank = blockIdx.x & 7;
            #pragma unroll
            for (int k = 0; k < 6; k++)
                if (acc[k] != 0.0) atomicAdd(&g_accB[k][bank], acc[k]);
            if (acc[6] != 0.0)
                atomicAdd(&g_obj2B[blockIdx.x & 31], -acc[6]);
            if (np) atomicAdd(&g_npos, np);
        }
    }

    // ===== ticket + finalize: tid 0 only; other threads already done =====
    if (tid != 0) return;
    __threadfence();                       // release this block's atomics
    int ticket = atomicAdd(&g_done, 1);
    if (ticket == BLOCKS - 1) {
        __threadfence();                   // acquire all blocks' atomics
        const double N = (double)NCELLS;
        double a[6];
        #pragma unroll
        for (int k = 0; k < 6; k++) {
            double s = 0.0;
            #pragma unroll
            for (int j = 0; j < 8; j++) s += g_accB[k][j];
            a[k] = s;
        }
        double o2 = 0.0;
        #pragma unroll
        for (int j = 0; j < 32; j++) o2 += g_obj2B[j];
        int np = g_npos;
        out[0] = (float)(a[0] / N * 2.5);
        out[1] = (float)(a[1] / N * 2.5);
        out[2] = (float)(a[2] / N * 2.5);
        out[3] = (float)(a[3] / N * 2.5);
        out[4] = (float)(a[4] / N + 0.5 * o2 / N);
        double dn = (double)np * (double)NC;
        if (dn < 1.0) dn = 1.0;
        out[5] = (float)(a[5] / dn);
        // reset for next graph replay
        #pragma unroll
        for (int k = 0; k < 6; k++)
            #pragma unroll
            for (int j = 0; j < 8; j++) g_accB[k][j] = 0.0;
        #pragma unroll
        for (int j = 0; j < 32; j++) g_obj2B[j] = 0.0;
        g_npos = 0; g_done = 0;
    }
}

extern "C" void kernel_launch(void* const* d_in, const int* in_sizes, int n_in,
                              void* d_out, int out_size) {
    const float* a0 = (const float*)d_in[0];
    const float* a1 = (const float*)d_in[1];
    const float* inp;
    const float* tg;
    if (in_sizes[0] == BS * TT * 5) { tg = a0; inp = a1; }
    else                            { inp = a0; tg = a1; }

    k_fused<<<BLOCKS, THREADS>>>(inp, tg, (float*)d_out);
}